// round 1
// baseline (speedup 1.0000x reference)
#include <cuda_runtime.h>
#include <cuda_bf16.h>

#define BB 32
#define SS 512
#define DD 768
#define OO 768
#define EE 8

// ---------------- scratch (device globals; no allocation allowed) ----------
__device__ float g_pooled[BB * DD];
__device__ float g_gate_val[BB * 2];
__device__ int   g_gate_idx[BB * 2];

// ---------------- kernel 1: pooled = x.mean(-2) ----------------------------
// grid (B, D/256), 256 threads; coalesced over d, loop over s.
__global__ void smoe_pool_kernel(const float* __restrict__ x) {
    const int b = blockIdx.x;
    const int d = blockIdx.y * 256 + threadIdx.x;
    const float* xp = x + (size_t)b * SS * DD + d;
    float sum = 0.f;
#pragma unroll 8
    for (int s = 0; s < SS; s++) sum += xp[(size_t)s * DD];
    g_pooled[b * DD + d] = sum * (1.0f / SS);
}

// ---------------- kernel 2: gating + top-2 softmax + aux loss ---------------
__device__ __forceinline__ float cv_squared8(const float* v) {
    float m = 0.f;
#pragma unroll
    for (int e = 0; e < EE; e++) m += v[e];
    m *= (1.0f / EE);
    float var = 0.f;
#pragma unroll
    for (int e = 0; e < EE; e++) { float dv = v[e] - m; var += dv * dv; }
    var *= (1.0f / (EE - 1));           // ddof=1
    return var / (m * m + 1e-10f);
}

__global__ void smoe_gate_kernel(const float* __restrict__ w_gate,
                                 float* __restrict__ loss_out) {
    const int b = threadIdx.x;          // 32 threads, one per batch row
    __shared__ float sh_gates[BB][EE];

    float logits[EE];
#pragma unroll
    for (int e = 0; e < EE; e++) logits[e] = 0.f;

    const float* p = g_pooled + b * DD;
    for (int d = 0; d < DD; d++) {
        float pv = p[d];
#pragma unroll
        for (int e = 0; e < EE; e++) logits[e] += pv * w_gate[d * EE + e];
    }

    // top-2, ties -> lowest index (strict > like jax top_k first occurrence)
    int i1 = 0; float v1 = logits[0];
#pragma unroll
    for (int e = 1; e < EE; e++) if (logits[e] > v1) { v1 = logits[e]; i1 = e; }
    int i2 = -1; float v2 = -1e30f;
#pragma unroll
    for (int e = 0; e < EE; e++)
        if (e != i1 && logits[e] > v2) { v2 = logits[e]; i2 = e; }

    // softmax over [v1, v2]  (v1 >= v2)
    float ex = expf(v2 - v1);
    float inv = 1.0f / (1.0f + ex);
    float gtop = inv;
    float gsec = ex * inv;

#pragma unroll
    for (int e = 0; e < EE; e++) sh_gates[b][e] = 0.f;
    sh_gates[b][i1] = gtop;
    sh_gates[b][i2] = gsec;

    g_gate_idx[b * 2 + 0] = i1;
    g_gate_idx[b * 2 + 1] = i2;
    g_gate_val[b * 2 + 0] = gtop;
    g_gate_val[b * 2 + 1] = gsec;

    __syncthreads();

    if (b == 0) {
        float imp[EE], ldv[EE];
#pragma unroll
        for (int e = 0; e < EE; e++) {
            float s = 0.f, c = 0.f;
            for (int bi = 0; bi < BB; bi++) {
                float g = sh_gates[bi][e];
                s += g;
                if (g > 0.f) c += 1.f;
            }
            imp[e] = s; ldv[e] = c;
        }
        loss_out[0] = (cv_squared8(imp) + cv_squared8(ldv)) * 0.01f;
    }
}

// ---------------- kernel 3: y[b] = x[b] @ (g0*W[e0]+g1*W[e1])^T + bc --------
// Classic 128x128x8 register-blocked SGEMM (TM=TN=8, 256 threads).
// Expert weight combine fused into the B-tile global->shared load.
__global__ __launch_bounds__(256, 2)
void smoe_gemm_kernel(const float* __restrict__ x,
                      const float* __restrict__ weight,
                      const float* __restrict__ bias,
                      float* __restrict__ out) {
    const int b = blockIdx.z;
    const int e0 = g_gate_idx[b * 2 + 0];
    const int e1 = g_gate_idx[b * 2 + 1];
    const float g0 = g_gate_val[b * 2 + 0];
    const float g1 = g_gate_val[b * 2 + 1];

    const int nBlk = blockIdx.x * 128;   // output-feature tile
    const int mBlk = blockIdx.y * 128;   // sequence tile

    const float* A  = x      + (size_t)b  * SS * DD + (size_t)mBlk * DD;
    const float* W0 = weight + (size_t)e0 * OO * DD + (size_t)nBlk * DD;
    const float* W1 = weight + (size_t)e1 * OO * DD + (size_t)nBlk * DD;

    __shared__ float As[8][128];
    __shared__ float Bs[8][128];

    const int tid = threadIdx.x;
    const int tx = tid & 15;             // 0..15 -> 8 cols each
    const int ty = tid >> 4;             // 0..15 -> 8 rows each

    const int lRow = tid >> 1;           // 0..127 tile row for loads
    const int lCol = (tid & 1) * 4;      // 0 or 4 (float4 along K)

    float acc[8][8];
#pragma unroll
    for (int i = 0; i < 8; i++)
#pragma unroll
        for (int j = 0; j < 8; j++) acc[i][j] = 0.f;

    for (int kt = 0; kt < DD; kt += 8) {
        // global -> shared (transposed to [k][row])
        float4 a4  = *(const float4*)(A  + (size_t)lRow * DD + kt + lCol);
        float4 w04 = *(const float4*)(W0 + (size_t)lRow * DD + kt + lCol);
        float4 w14 = *(const float4*)(W1 + (size_t)lRow * DD + kt + lCol);

        As[lCol + 0][lRow] = a4.x;
        As[lCol + 1][lRow] = a4.y;
        As[lCol + 2][lRow] = a4.z;
        As[lCol + 3][lRow] = a4.w;

        Bs[lCol + 0][lRow] = g0 * w04.x + g1 * w14.x;
        Bs[lCol + 1][lRow] = g0 * w04.y + g1 * w14.y;
        Bs[lCol + 2][lRow] = g0 * w04.z + g1 * w14.z;
        Bs[lCol + 3][lRow] = g0 * w04.w + g1 * w14.w;

        __syncthreads();

#pragma unroll
        for (int k = 0; k < 8; k++) {
            float ra[8], rb[8];
            *(float4*)&ra[0] = *(const float4*)&As[k][ty * 8 + 0];
            *(float4*)&ra[4] = *(const float4*)&As[k][ty * 8 + 4];
            *(float4*)&rb[0] = *(const float4*)&Bs[k][tx * 8 + 0];
            *(float4*)&rb[4] = *(const float4*)&Bs[k][tx * 8 + 4];
#pragma unroll
            for (int i = 0; i < 8; i++)
#pragma unroll
                for (int j = 0; j < 8; j++)
                    acc[i][j] += ra[i] * rb[j];
        }
        __syncthreads();
    }

    // epilogue: + combined bias, vectorized stores
    float bb[8];
#pragma unroll
    for (int j = 0; j < 8; j++) {
        int n = nBlk + tx * 8 + j;
        bb[j] = g0 * bias[e0 * OO + n] + g1 * bias[e1 * OO + n];
    }

    float* Cbase = out + (size_t)b * SS * OO + (size_t)nBlk + (size_t)tx * 8;
#pragma unroll
    for (int i = 0; i < 8; i++) {
        int m = mBlk + ty * 8 + i;
        float* cp = Cbase + (size_t)m * OO;
        float4 v0, v1v;
        v0.x  = acc[i][0] + bb[0]; v0.y  = acc[i][1] + bb[1];
        v0.z  = acc[i][2] + bb[2]; v0.w  = acc[i][3] + bb[3];
        v1v.x = acc[i][4] + bb[4]; v1v.y = acc[i][5] + bb[5];
        v1v.z = acc[i][6] + bb[6]; v1v.w = acc[i][7] + bb[7];
        *(float4*)(cp + 0) = v0;
        *(float4*)(cp + 4) = v1v;
    }
}

// ---------------- launch ----------------------------------------------------
extern "C" void kernel_launch(void* const* d_in, const int* in_sizes, int n_in,
                              void* d_out, int out_size) {
    const float* x      = (const float*)d_in[0];  // (32,512,768)
    const float* w_gate = (const float*)d_in[1];  // (768,8)
    const float* weight = (const float*)d_in[2];  // (8,768,768)
    const float* bias   = (const float*)d_in[3];  // (8,768)
    float* out = (float*)d_out;                   // y (32*512*768) then loss
    float* loss_out = out + (out_size - 1);

    smoe_pool_kernel<<<dim3(BB, DD / 256), 256>>>(x);
    smoe_gate_kernel<<<1, BB>>>(w_gate, loss_out);
    smoe_gemm_kernel<<<dim3(OO / 128, SS / 128, BB), 256>>>(x, weight, bias, out);
}

// round 2
// speedup vs baseline: 2.0438x; 2.0438x over previous
#include <cuda_runtime.h>
#include <cuda_bf16.h>
#include <cstdint>

#define BB 32
#define SS 512
#define DD 768
#define OO 768
#define EE 8

#define BM 128
#define BN 128
#define BK 32
#define KCH (DD / BK)          // 24 k-chunks
#define LDA 36                 // padded row stride (floats) -> conflict-free ldmatrix
#define BUFSZ (128 * LDA)      // floats per tile buffer

// ---------------- scratch (device globals; no allocation allowed) ----------
__device__ float g_pool_part[4 * BB * DD];
__device__ float g_gate_val[BB * 2];
__device__ int   g_gate_idx[BB * 2];

// ---------------- kernel 1: partial pooled sums -----------------------------
// grid (B, 4 s-chunks, D/256), 256 threads. 384 CTAs -> fills the chip.
__global__ void smoe_pool_kernel(const float* __restrict__ x) {
    const int b = blockIdx.x;
    const int sc = blockIdx.y;
    const int d = blockIdx.z * 256 + threadIdx.x;
    const float* xp = x + (size_t)b * SS * DD + (size_t)sc * 128 * DD + d;
    float sum = 0.f;
#pragma unroll 8
    for (int i = 0; i < 128; i++) sum += xp[(size_t)i * DD];
    g_pool_part[(sc * BB + b) * DD + d] = sum;
}

// ---------------- kernel 2: gating + top-2 softmax + aux loss ---------------
__device__ __forceinline__ float cv_squared8(const float* v) {
    float m = 0.f;
#pragma unroll
    for (int e = 0; e < EE; e++) m += v[e];
    m *= (1.0f / EE);
    float var = 0.f;
#pragma unroll
    for (int e = 0; e < EE; e++) { float dv = v[e] - m; var += dv * dv; }
    var *= (1.0f / (EE - 1));
    return var / (m * m + 1e-10f);
}

__global__ void smoe_gate_kernel(const float* __restrict__ w_gate,
                                 float* __restrict__ loss_out) {
    const int b = threadIdx.x;          // 32 threads, one per batch row
    __shared__ float sh_gates[BB][EE];

    float logits[EE];
#pragma unroll
    for (int e = 0; e < EE; e++) logits[e] = 0.f;

    for (int d = 0; d < DD; d++) {
        float pv = (g_pool_part[0 * BB * DD + b * DD + d] +
                    g_pool_part[1 * BB * DD + b * DD + d] +
                    g_pool_part[2 * BB * DD + b * DD + d] +
                    g_pool_part[3 * BB * DD + b * DD + d]) * (1.0f / SS);
#pragma unroll
        for (int e = 0; e < EE; e++) logits[e] += pv * w_gate[d * EE + e];
    }

    int i1 = 0; float v1 = logits[0];
#pragma unroll
    for (int e = 1; e < EE; e++) if (logits[e] > v1) { v1 = logits[e]; i1 = e; }
    int i2 = -1; float v2 = -1e30f;
#pragma unroll
    for (int e = 0; e < EE; e++)
        if (e != i1 && logits[e] > v2) { v2 = logits[e]; i2 = e; }

    float ex = expf(v2 - v1);
    float inv = 1.0f / (1.0f + ex);
    float gtop = inv;
    float gsec = ex * inv;

#pragma unroll
    for (int e = 0; e < EE; e++) sh_gates[b][e] = 0.f;
    sh_gates[b][i1] = gtop;
    sh_gates[b][i2] = gsec;

    g_gate_idx[b * 2 + 0] = i1;
    g_gate_idx[b * 2 + 1] = i2;
    g_gate_val[b * 2 + 0] = gtop;
    g_gate_val[b * 2 + 1] = gsec;

    __syncthreads();

    if (b == 0) {
        float imp[EE], ldv[EE];
#pragma unroll
        for (int e = 0; e < EE; e++) {
            float s = 0.f, c = 0.f;
            for (int bi = 0; bi < BB; bi++) {
                float g = sh_gates[bi][e];
                s += g;
                if (g > 0.f) c += 1.f;
            }
            imp[e] = s; ldv[e] = c;
        }
        loss_out[0] = (cv_squared8(imp) + cv_squared8(ldv)) * 0.01f;
    }
}

// ---------------- kernel 3: TF32 tensor-core GEMM ---------------------------
// y[b] = x[b] @ (g0*W[e0] + g1*W[e1])^T + combined_bias
// 128x128x32 CTA tile, 8 warps (2x4), warp tile 64x32, mma.m16n8k8.tf32.
// A / W0 / W1 streamed by cp.async (double-buffered); expert combine done in
// registers on the B fragments after ldmatrix.

__device__ __forceinline__ uint32_t smem_u32(const void* p) {
    return (uint32_t)__cvta_generic_to_shared(p);
}

__device__ __forceinline__ void ldsm_x4(uint32_t (&r)[4], uint32_t addr) {
    asm volatile("ldmatrix.sync.aligned.m8n8.x4.shared.b16 {%0,%1,%2,%3}, [%4];"
                 : "=r"(r[0]), "=r"(r[1]), "=r"(r[2]), "=r"(r[3]) : "r"(addr));
}

__device__ __forceinline__ void mma_tf32(float (&d)[4], const uint32_t (&a)[4],
                                         uint32_t b0, uint32_t b1) {
    asm volatile(
        "mma.sync.aligned.m16n8k8.row.col.f32.tf32.tf32.f32 "
        "{%0,%1,%2,%3}, {%4,%5,%6,%7}, {%8,%9}, {%0,%1,%2,%3};"
        : "+f"(d[0]), "+f"(d[1]), "+f"(d[2]), "+f"(d[3])
        : "r"(a[0]), "r"(a[1]), "r"(a[2]), "r"(a[3]), "r"(b0), "r"(b1));
}

__device__ __forceinline__ void cp_async16(uint32_t dst, const float* src) {
    asm volatile("cp.async.ca.shared.global [%0], [%1], 16;" :: "r"(dst), "l"(src));
}

__global__ __launch_bounds__(256, 2)
void smoe_gemm_tf32(const float* __restrict__ x,
                    const float* __restrict__ weight,
                    const float* __restrict__ bias,
                    float* __restrict__ out) {
    extern __shared__ float sm[];
    float* As  = sm;                 // [2][BUFSZ]
    float* B0s = sm + 2 * BUFSZ;     // [2][BUFSZ]
    float* B1s = sm + 4 * BUFSZ;     // [2][BUFSZ]

    const int b = blockIdx.z;
    const int e0 = g_gate_idx[2 * b], e1 = g_gate_idx[2 * b + 1];
    const float g0 = g_gate_val[2 * b], g1 = g_gate_val[2 * b + 1];
    const int nBlk = blockIdx.x * BN;
    const int mBlk = blockIdx.y * BM;

    const int tid = threadIdx.x;
    const int lane = tid & 31;
    const int wid = tid >> 5;
    const int warpM = wid >> 2;      // 0..1 -> 64-row slab
    const int warpN = wid & 3;       // 0..3 -> 32-col slab

    const float* gA  = x      + (size_t)b  * SS * DD + (size_t)mBlk * DD;
    const float* gW0 = weight + (size_t)e0 * OO * DD + (size_t)nBlk * DD;
    const float* gW1 = weight + (size_t)e1 * OO * DD + (size_t)nBlk * DD;

    // ldmatrix source offsets (floats, within a buffer)
    // A frag (16x8): tiles [rows0-7,k0-3][rows8-15,k0-3][rows0-7,k4-7][rows8-15,k4-7]
    const int aRow = (lane & 7) + ((lane >> 3) & 1) * 8;
    const int aK   = ((lane >> 4) & 1) * 4;
    int aOff[4];
#pragma unroll
    for (int mf = 0; mf < 4; mf++)
        aOff[mf] = (warpM * 64 + mf * 16 + aRow) * LDA + aK;

    // B pair (two n-frags, 16 rows): tiles [nf0,k0-3][nf0,k4-7][nf1,k0-3][nf1,k4-7]
    const int bRow = (lane & 7) + ((lane >> 4) & 1) * 8;
    const int bK   = ((lane >> 3) & 1) * 4;
    int bOff[2];
#pragma unroll
    for (int p = 0; p < 2; p++)
        bOff[p] = (warpN * 32 + p * 16 + bRow) * LDA + bK;

    float acc[4][4][4];
#pragma unroll
    for (int i = 0; i < 4; i++)
#pragma unroll
        for (int j = 0; j < 4; j++)
#pragma unroll
            for (int k = 0; k < 4; k++) acc[i][j][k] = 0.f;

    // --- cp.async tile loader: 128x32 floats per stream, 16B per op ---------
    auto issue = [&](int chunk, int buf) {
        const int kt = chunk * BK;
#pragma unroll
        for (int p = 0; p < 4; p++) {
            int c = tid + p * 256;
            int m = c >> 3;
            int k4 = (c & 7) * 4;
            int so = buf * BUFSZ + m * LDA + k4;
            size_t go = (size_t)m * DD + kt + k4;
            cp_async16(smem_u32(As  + so), gA  + go);
            cp_async16(smem_u32(B0s + so), gW0 + go);
            cp_async16(smem_u32(B1s + so), gW1 + go);
        }
        asm volatile("cp.async.commit_group;");
    };

    issue(0, 0);

#pragma unroll 1
    for (int c = 0; c < KCH; c++) {
        const int buf = c & 1;
        if (c + 1 < KCH) {
            issue(c + 1, buf ^ 1);
            asm volatile("cp.async.wait_group 1;");
        } else {
            asm volatile("cp.async.wait_group 0;");
        }
        __syncthreads();

        const int bo = buf * BUFSZ;
#pragma unroll
        for (int kk = 0; kk < BK; kk += 8) {
            uint32_t a[4][4];
#pragma unroll
            for (int mf = 0; mf < 4; mf++)
                ldsm_x4(a[mf], smem_u32(As + bo + aOff[mf] + kk));

#pragma unroll
            for (int p = 0; p < 2; p++) {
                uint32_t w0[4], w1[4];
                ldsm_x4(w0, smem_u32(B0s + bo + bOff[p] + kk));
                ldsm_x4(w1, smem_u32(B1s + bo + bOff[p] + kk));
                uint32_t bc[4];
#pragma unroll
                for (int i = 0; i < 4; i++) {
                    float v = g0 * __uint_as_float(w0[i]) + g1 * __uint_as_float(w1[i]);
                    bc[i] = __float_as_uint(v);
                }
#pragma unroll
                for (int mf = 0; mf < 4; mf++) {
                    mma_tf32(acc[mf][2 * p + 0], a[mf], bc[0], bc[1]);
                    mma_tf32(acc[mf][2 * p + 1], a[mf], bc[2], bc[3]);
                }
            }
        }
        __syncthreads();
    }

    // --- epilogue: combined bias + float2 stores ----------------------------
    float2 bb[4];
#pragma unroll
    for (int nf = 0; nf < 4; nf++) {
        int n = nBlk + warpN * 32 + nf * 8 + (lane & 3) * 2;
        bb[nf].x = g0 * bias[e0 * OO + n]     + g1 * bias[e1 * OO + n];
        bb[nf].y = g0 * bias[e0 * OO + n + 1] + g1 * bias[e1 * OO + n + 1];
    }

    float* C = out + (size_t)b * SS * OO;
#pragma unroll
    for (int mf = 0; mf < 4; mf++) {
        int m = mBlk + warpM * 64 + mf * 16 + (lane >> 2);
#pragma unroll
        for (int nf = 0; nf < 4; nf++) {
            int n = nBlk + warpN * 32 + nf * 8 + (lane & 3) * 2;
            float2 v0, v1;
            v0.x = acc[mf][nf][0] + bb[nf].x;
            v0.y = acc[mf][nf][1] + bb[nf].y;
            v1.x = acc[mf][nf][2] + bb[nf].x;
            v1.y = acc[mf][nf][3] + bb[nf].y;
            *(float2*)(C + (size_t)m * OO + n) = v0;
            *(float2*)(C + (size_t)(m + 8) * OO + n) = v1;
        }
    }
}

// ---------------- launch ----------------------------------------------------
extern "C" void kernel_launch(void* const* d_in, const int* in_sizes, int n_in,
                              void* d_out, int out_size) {
    const float* x      = (const float*)d_in[0];  // (32,512,768)
    const float* w_gate = (const float*)d_in[1];  // (768,8)
    const float* weight = (const float*)d_in[2];  // (8,768,768)
    const float* bias   = (const float*)d_in[3];  // (8,768)
    float* out = (float*)d_out;
    float* loss_out = out + (out_size - 1);

    const int smem_bytes = 6 * BUFSZ * 4;  // 110592 B (A/W0/W1 double-buffered)
    cudaFuncSetAttribute(smoe_gemm_tf32,
                         cudaFuncAttributeMaxDynamicSharedMemorySize, smem_bytes);

    smoe_pool_kernel<<<dim3(BB, 4, DD / 256), 256>>>(x);
    smoe_gate_kernel<<<1, BB>>>(w_gate, loss_out);
    smoe_gemm_tf32<<<dim3(OO / BN, SS / BM, BB), 256, smem_bytes>>>(x, weight, bias, out);
}